// round 3
// baseline (speedup 1.0000x reference)
#include <cuda_runtime.h>
#include <cuda_bf16.h>
#include <cstdint>

#define NROWS   262144
#define NSEG    1024
#define HID     256
#define KDIM    256

// ---------------- scratch (device globals: no allocations allowed) ----------
__device__ float          g_scores[NROWS];
__device__ __nv_bfloat16  g_w1t[HID * KDIM];   // W1^T as bf16, [n][k]
__device__ int            g_segstart[NSEG + 1];

// ---------------- helpers ----------------------------------------------------
static __device__ __forceinline__ uint32_t smem_u32(const void* p) {
    uint32_t a;
    asm("{ .reg .u64 t; cvta.to.shared.u64 t, %1; cvt.u32.u64 %0, t; }"
        : "=r"(a) : "l"(p));
    return a;
}

static __device__ __forceinline__ void ldsm_x4(uint32_t a, uint32_t& r0, uint32_t& r1,
                                               uint32_t& r2, uint32_t& r3) {
    asm volatile("ldmatrix.sync.aligned.m8n8.x4.shared.b16 {%0,%1,%2,%3}, [%4];"
                 : "=r"(r0), "=r"(r1), "=r"(r2), "=r"(r3) : "r"(a));
}

static __device__ __forceinline__ void mma_bf16(float* c,
                                                uint32_t a0, uint32_t a1, uint32_t a2, uint32_t a3,
                                                uint32_t b0, uint32_t b1) {
    asm volatile("mma.sync.aligned.m16n8k16.row.col.f32.bf16.bf16.f32 "
                 "{%0,%1,%2,%3}, {%4,%5,%6,%7}, {%8,%9}, {%0,%1,%2,%3};"
                 : "+f"(c[0]), "+f"(c[1]), "+f"(c[2]), "+f"(c[3])
                 : "r"(a0), "r"(a1), "r"(a2), "r"(a3), "r"(b0), "r"(b1));
}

// pack two floats into bf16x2 (hi) and return residuals
static __device__ __forceinline__ uint32_t pack_hi(float a, float b, float& ra, float& rb) {
    __nv_bfloat16 ha = __float2bfloat16(a), hb = __float2bfloat16(b);
    ra = a - __bfloat162float(ha);
    rb = b - __bfloat162float(hb);
    return (uint32_t)__bfloat16_as_ushort(ha) | ((uint32_t)__bfloat16_as_ushort(hb) << 16);
}
static __device__ __forceinline__ uint32_t pack_lo(float ra, float rb) {
    return (uint32_t)__bfloat16_as_ushort(__float2bfloat16(ra))
         | ((uint32_t)__bfloat16_as_ushort(__float2bfloat16(rb)) << 16);
}

// ---------------- kernel 1: W1^T -> bf16 [n][k] ------------------------------
__global__ void k_w1t(const float* __restrict__ W1) {
    int k = blockIdx.x, n = threadIdx.x;
    g_w1t[n * KDIM + k] = __float2bfloat16(W1[k * HID + n]);
}

// ---------------- kernel 2: segment boundaries (batch sorted) ----------------
// batch may be int32 (JAX x64 disabled) or int64. Detect on device: under
// int64, odd 32-bit words near the buffer end are zero high-halves; under
// int32 they are batch values near 1023.
__global__ void k_bounds(const void* __restrict__ batch_raw) {
    const int* b32 = (const int*)batch_raw;
    bool is64 = (b32[NROWS - 1] == 0) && (b32[NROWS - 3] == 0) &&
                (b32[NROWS - 5] == 0) && (b32[NROWS - 7] == 0);
    int g = blockIdx.x * blockDim.x + threadIdx.x;
    if (g > NSEG) return;
    int lo = 0, hi = NROWS;
    while (lo < hi) {
        int mid = (lo + hi) >> 1;
        long long v = is64 ? ((const long long*)batch_raw)[mid] : (long long)b32[mid];
        if (v < (long long)g) lo = mid + 1; else hi = mid;
    }
    g_segstart[g] = lo;
}

// ---------------- kernel 3: scores via mma.sync bf16 (2-term x-split) --------
// Per CTA: M=128 rows, N=256 in 4 chunks of 64, K=256.
// smem layout (bytes):
#define SM_AHI 0          // 128 x 256 bf16, swizzled          (65536)
#define SM_ALO 65536      // residual tile                      (65536)
#define SM_B   131072     // 64 x 256 bf16 chunk of W1^T        (32768)
#define SM_SC  163840     // 128 f32 partial scores             (512)
#define SM_B1  164352     // 256 f32                            (1024)
#define SM_W2  165376     // 256 f32                            (1024)
#define SMEM_SCORES_TOTAL 166400

__global__ void __launch_bounds__(256, 1)
k_scores(const float* __restrict__ x, const float* __restrict__ b1,
         const float* __restrict__ W2, const float* __restrict__ b2) {
    extern __shared__ char smem[];
    uint32_t sb = smem_u32(smem);
    int tid = threadIdx.x, wid = tid >> 5, lid = tid & 31;
    size_t rowbase = (size_t)blockIdx.x * 128;
    int mw = wid & 3, nw = wid >> 2;              // warp grid: 4 (M) x 2 (N)

    // stage constants, zero score accumulator
    if (tid < 128) ((float*)(smem + SM_SC))[tid] = 0.f;
    ((float*)(smem + SM_B1))[tid] = b1[tid];
    ((float*)(smem + SM_W2))[tid] = W2[tid];

    // ---- stage A tile: 128x256 f32 -> bf16 hi/lo, 16B-chunk XOR swizzle ----
    {
        const float4* xp = (const float4*)(x + rowbase * 256);
        #pragma unroll
        for (int i = 0; i < 16; i++) {
            int cid = tid + i * 256;              // 0..4095 chunks of 8 elems
            int row = cid >> 5, c = cid & 31;
            float4 v0 = __ldg(&xp[row * 64 + c * 2]);
            float4 v1 = __ldg(&xp[row * 64 + c * 2 + 1]);
            float r0, r1, r2, r3, r4, r5, r6, r7;
            uint4 hi, lo;
            hi.x = pack_hi(v0.x, v0.y, r0, r1);
            hi.y = pack_hi(v0.z, v0.w, r2, r3);
            hi.z = pack_hi(v1.x, v1.y, r4, r5);
            hi.w = pack_hi(v1.z, v1.w, r6, r7);
            lo.x = pack_lo(r0, r1);
            lo.y = pack_lo(r2, r3);
            lo.z = pack_lo(r4, r5);
            lo.w = pack_lo(r6, r7);
            uint32_t off = row * 512 + ((c ^ (row & 7)) << 4);
            *(uint4*)(smem + SM_AHI + off) = hi;
            *(uint4*)(smem + SM_ALO + off) = lo;
        }
    }

    // ---- per-lane fragment address invariants ----
    int g = lid >> 2, t = lid & 3, r8 = lid & 7, j = lid >> 3;
    // A: ldmatrix.x4 tiles {(mb+r,kb),(mb+8+r,kb),(mb+r,kb+8),(mb+8+r,kb+8)}
    int arow = mw * 32 + (j & 1) * 8 + r8;        // for m-tile 0 (rows mb..mb+15)
    uint32_t aoff0 = SM_AHI + arow * 512;
    int arm = arow & 7, ac0 = j >> 1;
    // B: tiles {(nb+r,kb),(nb+r,kb+8),(nb+8+r,kb),(nb+8+r,kb+8)}
    int nloc = nw * 32 + (j >> 1) * 8 + r8;       // for n-tile pair 0
    uint32_t boff0 = SM_B + nloc * 512;
    int bnm = nloc & 7, bc0 = j & 1;

    const float* smB1 = (const float*)(smem + SM_B1);
    const float* smW2 = (const float*)(smem + SM_W2);
    float part[4] = {0.f, 0.f, 0.f, 0.f};         // rows mw*32 + {g, g+8, 16+g, 24+g}

    for (int ch = 0; ch < 4; ch++) {
        __syncthreads();                          // prev chunk's B reads done
        // stage B chunk: 64 n-rows x 256 k (bf16), swizzled
        {
            const uint4* wp = (const uint4*)(g_w1t + (ch * 64) * KDIM);
            #pragma unroll
            for (int i = 0; i < 8; i++) {
                int cid = tid + i * 256;          // 0..2047
                int nl = cid >> 5, c = cid & 31;
                uint4 v = wp[nl * 32 + c];
                *(uint4*)(smem + SM_B + nl * 512 + ((c ^ (nl & 7)) << 4)) = v;
            }
        }
        __syncthreads();

        float acc[2][4][4];
        #pragma unroll
        for (int a = 0; a < 2; a++)
            #pragma unroll
            for (int b = 0; b < 4; b++)
                #pragma unroll
                for (int cc = 0; cc < 4; cc++) acc[a][b][cc] = 0.f;

        #pragma unroll 4
        for (int ks = 0; ks < 16; ks++) {
            uint32_t sa = (uint32_t)(((2 * ks + ac0) ^ arm) << 4);
            uint32_t so = (uint32_t)(((2 * ks + bc0) ^ bnm) << 4);
            uint32_t ah0[4], ah1[4], al0[4], al1[4], b0[4], b1r[4];
            ldsm_x4(sb + aoff0 + sa,                 ah0[0], ah0[1], ah0[2], ah0[3]);
            ldsm_x4(sb + aoff0 + 8192 + sa,          ah1[0], ah1[1], ah1[2], ah1[3]);
            ldsm_x4(sb + aoff0 + 65536 + sa,         al0[0], al0[1], al0[2], al0[3]);
            ldsm_x4(sb + aoff0 + 65536 + 8192 + sa,  al1[0], al1[1], al1[2], al1[3]);
            ldsm_x4(sb + boff0 + so,                 b0[0], b0[1], b0[2], b0[3]);
            ldsm_x4(sb + boff0 + 8192 + so,          b1r[0], b1r[1], b1r[2], b1r[3]);

            mma_bf16(acc[0][0], ah0[0], ah0[1], ah0[2], ah0[3], b0[0],  b0[1]);
            mma_bf16(acc[0][1], ah0[0], ah0[1], ah0[2], ah0[3], b0[2],  b0[3]);
            mma_bf16(acc[0][2], ah0[0], ah0[1], ah0[2], ah0[3], b1r[0], b1r[1]);
            mma_bf16(acc[0][3], ah0[0], ah0[1], ah0[2], ah0[3], b1r[2], b1r[3]);
            mma_bf16(acc[1][0], ah1[0], ah1[1], ah1[2], ah1[3], b0[0],  b0[1]);
            mma_bf16(acc[1][1], ah1[0], ah1[1], ah1[2], ah1[3], b0[2],  b0[3]);
            mma_bf16(acc[1][2], ah1[0], ah1[1], ah1[2], ah1[3], b1r[0], b1r[1]);
            mma_bf16(acc[1][3], ah1[0], ah1[1], ah1[2], ah1[3], b1r[2], b1r[3]);
            mma_bf16(acc[0][0], al0[0], al0[1], al0[2], al0[3], b0[0],  b0[1]);
            mma_bf16(acc[0][1], al0[0], al0[1], al0[2], al0[3], b0[2],  b0[3]);
            mma_bf16(acc[0][2], al0[0], al0[1], al0[2], al0[3], b1r[0], b1r[1]);
            mma_bf16(acc[0][3], al0[0], al0[1], al0[2], al0[3], b1r[2], b1r[3]);
            mma_bf16(acc[1][0], al1[0], al1[1], al1[2], al1[3], b0[0],  b0[1]);
            mma_bf16(acc[1][1], al1[0], al1[1], al1[2], al1[3], b0[2],  b0[3]);
            mma_bf16(acc[1][2], al1[0], al1[1], al1[2], al1[3], b1r[0], b1r[1]);
            mma_bf16(acc[1][3], al1[0], al1[1], al1[2], al1[3], b1r[2], b1r[3]);
        }

        // chunk epilogue: fold h -> relu(h + b1) . W2 into per-row partials
        int colb = ch * 64 + nw * 32 + 2 * t;
        #pragma unroll
        for (int nt = 0; nt < 4; nt++) {
            float bv0 = smB1[colb + nt * 8],     bv1 = smB1[colb + nt * 8 + 1];
            float wv0 = smW2[colb + nt * 8],     wv1 = smW2[colb + nt * 8 + 1];
            #pragma unroll
            for (int mt = 0; mt < 2; mt++) {
                part[mt * 2 + 0] += fmaxf(acc[mt][nt][0] + bv0, 0.f) * wv0
                                  + fmaxf(acc[mt][nt][1] + bv1, 0.f) * wv1;
                part[mt * 2 + 1] += fmaxf(acc[mt][nt][2] + bv0, 0.f) * wv0
                                  + fmaxf(acc[mt][nt][3] + bv1, 0.f) * wv1;
            }
        }
    }

    // reduce over the 4 lanes (t) that share each row
    #pragma unroll
    for (int p = 0; p < 4; p++) {
        part[p] += __shfl_xor_sync(0xffffffffu, part[p], 1);
        part[p] += __shfl_xor_sync(0xffffffffu, part[p], 2);
    }
    if (t == 0) {
        float* sc = (float*)(smem + SM_SC);
        atomicAdd(&sc[mw * 32 + g],      part[0]);
        atomicAdd(&sc[mw * 32 + 8 + g],  part[1]);
        atomicAdd(&sc[mw * 32 + 16 + g], part[2]);
        atomicAdd(&sc[mw * 32 + 24 + g], part[3]);
    }
    __syncthreads();
    if (tid < 128)
        g_scores[rowbase + tid] = ((float*)(smem + SM_SC))[tid] + __ldg(b2);
}

// ---------------- kernel 4: segment softmax + weighted pooling --------------
__global__ void __launch_bounds__(256)
k_pool(const float* __restrict__ x, float* __restrict__ out) {
    __shared__ float wbuf[1024];
    __shared__ float red[256];
    int g = blockIdx.x, t = threadIdx.x;
    int s0 = g_segstart[g], s1 = g_segstart[g + 1];

    // segment max, clamped at >= 0 (scatter-amax-into-zeros semantics)
    float m = 0.f;
    for (int i = s0 + t; i < s1; i += 256) m = fmaxf(m, g_scores[i]);
    red[t] = m; __syncthreads();
    #pragma unroll
    for (int st = 128; st > 0; st >>= 1) {
        if (t < st) red[t] = fmaxf(red[t], red[t + st]);
        __syncthreads();
    }
    m = red[0]; __syncthreads();

    float den = 0.f, acc = 0.f;     // acc = dim t of this segment's output
    for (int base = s0; base < s1; base += 1024) {
        int n = min(1024, s1 - base);
        for (int i = t; i < n; i += 256) {
            float e = __expf(g_scores[base + i] - m);
            wbuf[i] = e;
            den += e;
        }
        __syncthreads();
        #pragma unroll 4
        for (int i = 0; i < n; i++)
            acc = fmaf(__ldg(&x[(size_t)(base + i) * 256 + t]), wbuf[i], acc);
        __syncthreads();
    }

    red[t] = den; __syncthreads();
    #pragma unroll
    for (int st = 128; st > 0; st >>= 1) {
        if (t < st) red[t] += red[t + st];
        __syncthreads();
    }
    den = red[0];
    out[g * 256 + t] = acc / (den + 1e-9f);
}

// ---------------- launch ----------------------------------------------------
extern "C" void kernel_launch(void* const* d_in, const int* in_sizes, int n_in,
                              void* d_out, int out_size) {
    // Resolve inputs by element count (robust to metadata ordering):
    //   x: 67108864, W1: 65536, batch: 262144, b2: 1, b1/W2: both 256 (keep
    //   relative order: b1 first, then W2 — matches signature & dict order).
    const float* x = 0; const float* W1 = 0; const float* b1 = 0;
    const float* W2 = 0; const float* b2 = 0; const void* batch = 0;
    for (int i = 0; i < n_in; i++) {
        switch (in_sizes[i]) {
            case 67108864: x = (const float*)d_in[i]; break;
            case 65536:    W1 = (const float*)d_in[i]; break;
            case 262144:   batch = d_in[i]; break;
            case 1:        b2 = (const float*)d_in[i]; break;
            case 256:
                if (!b1) b1 = (const float*)d_in[i];
                else     W2 = (const float*)d_in[i];
                break;
            default: break;
        }
    }
    // positional fallback (signature order: x, W1, b1, W2, b2, batch)
    if (!x)     x     = (const float*)d_in[0];
    if (!W1)    W1    = (const float*)d_in[1];
    if (!b1)    b1    = (const float*)d_in[2];
    if (!W2)    W2    = (const float*)d_in[3];
    if (!b2)    b2    = (const float*)d_in[4];
    if (!batch) batch = d_in[5];

    cudaFuncSetAttribute(k_scores, cudaFuncAttributeMaxDynamicSharedMemorySize,
                         SMEM_SCORES_TOTAL);

    k_w1t<<<KDIM, HID>>>(W1);
    k_bounds<<<5, 256>>>(batch);
    k_scores<<<NROWS / 128, 256, SMEM_SCORES_TOTAL>>>(x, b1, W2, b2);
    k_pool<<<NSEG, 256>>>(x, (float*)d_out);
}

// round 4
// speedup vs baseline: 1.5748x; 1.5748x over previous
#include <cuda_runtime.h>
#include <cuda_fp16.h>
#include <cstdint>

#define NROWS   262144
#define NSEG    1024
#define HID     256
#define KDIM    256

// ---------------- scratch (device globals: no allocations allowed) ----------
__device__ float  g_scores[NROWS];
__device__ __half g_w1t[HID * KDIM];   // W1^T as fp16, [n][k]
__device__ int    g_segstart[NSEG + 1];

// ---------------- helpers ----------------------------------------------------
static __device__ __forceinline__ uint32_t smem_u32(const void* p) {
    uint32_t a;
    asm("{ .reg .u64 t; cvta.to.shared.u64 t, %1; cvt.u32.u64 %0, t; }"
        : "=r"(a) : "l"(p));
    return a;
}

static __device__ __forceinline__ void ldsm_x4(uint32_t a, uint32_t& r0, uint32_t& r1,
                                               uint32_t& r2, uint32_t& r3) {
    asm volatile("ldmatrix.sync.aligned.m8n8.x4.shared.b16 {%0,%1,%2,%3}, [%4];"
                 : "=r"(r0), "=r"(r1), "=r"(r2), "=r"(r3) : "r"(a));
}

static __device__ __forceinline__ void mma_f16(float* c,
                                               uint32_t a0, uint32_t a1, uint32_t a2, uint32_t a3,
                                               uint32_t b0, uint32_t b1) {
    asm volatile("mma.sync.aligned.m16n8k16.row.col.f32.f16.f16.f32 "
                 "{%0,%1,%2,%3}, {%4,%5,%6,%7}, {%8,%9}, {%0,%1,%2,%3};"
                 : "+f"(c[0]), "+f"(c[1]), "+f"(c[2]), "+f"(c[3])
                 : "r"(a0), "r"(a1), "r"(a2), "r"(a3), "r"(b0), "r"(b1));
}

static __device__ __forceinline__ uint32_t pack_h2(float a, float b) {
    __half2 h = __floats2half2_rn(a, b);
    return *(uint32_t*)&h;
}

// ---------------- kernel 1: W1^T -> fp16 [n][k] ------------------------------
__global__ void k_w1t(const float* __restrict__ W1) {
    int k = blockIdx.x, n = threadIdx.x;
    g_w1t[n * KDIM + k] = __float2half_rn(W1[k * HID + n]);
}

// ---------------- kernel 2: segment boundaries (batch sorted) ----------------
// batch may be int32 (JAX x64 disabled) or int64; detect on device.
__global__ void k_bounds(const void* __restrict__ batch_raw) {
    const int* b32 = (const int*)batch_raw;
    bool is64 = (b32[NROWS - 1] == 0) && (b32[NROWS - 3] == 0) &&
                (b32[NROWS - 5] == 0) && (b32[NROWS - 7] == 0);
    int g = blockIdx.x * blockDim.x + threadIdx.x;
    if (g > NSEG) return;
    int lo = 0, hi = NROWS;
    while (lo < hi) {
        int mid = (lo + hi) >> 1;
        long long v = is64 ? ((const long long*)batch_raw)[mid] : (long long)b32[mid];
        if (v < (long long)g) lo = mid + 1; else hi = mid;
    }
    g_segstart[g] = lo;
}

// ---------------- kernel 3: scores via mma.sync fp16 (single term) -----------
// Per CTA: M=128 rows, N=256 in 4 chunks of 64, K=256. 2 CTAs/SM.
#define SM_A   0          // 128 x 256 fp16, swizzled           (65536)
#define SM_B   65536      // 64 x 256 fp16 chunk of W1^T        (32768)
#define SM_SC  98304      // 128 f32 partial scores             (512)
#define SM_B1  98816      // 256 f32                            (1024)
#define SM_W2  99840      // 256 f32                            (1024)
#define SMEM_SCORES_TOTAL 100864

__global__ void __launch_bounds__(256, 2)
k_scores(const float* __restrict__ x, const float* __restrict__ b1,
         const float* __restrict__ W2, const float* __restrict__ b2) {
    extern __shared__ char smem[];
    uint32_t sb = smem_u32(smem);
    int tid = threadIdx.x, wid = tid >> 5, lid = tid & 31;
    size_t rowbase = (size_t)blockIdx.x * 128;
    int mw = wid & 3, nw = wid >> 2;              // warp grid: 4 (M) x 2 (N)

    // stage constants, zero score accumulator
    if (tid < 128) ((float*)(smem + SM_SC))[tid] = 0.f;
    ((float*)(smem + SM_B1))[tid] = b1[tid];
    ((float*)(smem + SM_W2))[tid] = W2[tid];

    // ---- stage A tile: 128x256 f32 -> fp16, 16B-chunk XOR swizzle ----
    {
        const float4* xp = (const float4*)(x + rowbase * 256);
        #pragma unroll
        for (int i = 0; i < 16; i++) {
            int cid = tid + i * 256;              // 0..4095 chunks of 8 elems
            int row = cid >> 5, c = cid & 31;
            float4 v0 = __ldg(&xp[row * 64 + c * 2]);
            float4 v1 = __ldg(&xp[row * 64 + c * 2 + 1]);
            uint4 hv;
            hv.x = pack_h2(v0.x, v0.y);
            hv.y = pack_h2(v0.z, v0.w);
            hv.z = pack_h2(v1.x, v1.y);
            hv.w = pack_h2(v1.z, v1.w);
            uint32_t off = row * 512 + ((c ^ (row & 7)) << 4);
            *(uint4*)(smem + SM_A + off) = hv;
        }
    }

    // ---- per-lane fragment address invariants ----
    int g = lid >> 2, t = lid & 3, r8 = lid & 7, j = lid >> 3;
    // A: ldmatrix.x4 tiles {(mb+r,kb),(mb+8+r,kb),(mb+r,kb+8),(mb+8+r,kb+8)}
    int arow = mw * 32 + (j & 1) * 8 + r8;
    uint32_t aoff0 = SM_A + arow * 512;
    int arm = arow & 7, ac0 = j >> 1;
    // B: tiles {(nb+r,kb),(nb+r,kb+8),(nb+8+r,kb),(nb+8+r,kb+8)}
    int nloc = nw * 32 + (j >> 1) * 8 + r8;
    uint32_t boff0 = SM_B + nloc * 512;
    int bnm = nloc & 7, bc0 = j & 1;

    const float* smB1 = (const float*)(smem + SM_B1);
    const float* smW2 = (const float*)(smem + SM_W2);
    float part[4] = {0.f, 0.f, 0.f, 0.f};         // rows mw*32 + {g, g+8, 16+g, 24+g}

    for (int ch = 0; ch < 4; ch++) {
        __syncthreads();                          // prev chunk's B reads done
        // stage B chunk: 64 n-rows x 256 k (fp16), swizzled
        {
            const uint4* wp = (const uint4*)(g_w1t + (ch * 64) * KDIM);
            #pragma unroll
            for (int i = 0; i < 8; i++) {
                int cid = tid + i * 256;          // 0..2047
                int nl = cid >> 5, c = cid & 31;
                uint4 v = wp[nl * 32 + c];
                *(uint4*)(smem + SM_B + nl * 512 + ((c ^ (nl & 7)) << 4)) = v;
            }
        }
        __syncthreads();

        float acc[2][4][4];
        #pragma unroll
        for (int a = 0; a < 2; a++)
            #pragma unroll
            for (int b = 0; b < 4; b++)
                #pragma unroll
                for (int cc = 0; cc < 4; cc++) acc[a][b][cc] = 0.f;

        #pragma unroll 4
        for (int ks = 0; ks < 16; ks++) {
            uint32_t sa = (uint32_t)(((2 * ks + ac0) ^ arm) << 4);
            uint32_t so = (uint32_t)(((2 * ks + bc0) ^ bnm) << 4);
            uint32_t a0[4], a1[4], b0[4], b1r[4];
            ldsm_x4(sb + aoff0 + sa,        a0[0], a0[1], a0[2], a0[3]);
            ldsm_x4(sb + aoff0 + 8192 + sa, a1[0], a1[1], a1[2], a1[3]);
            ldsm_x4(sb + boff0 + so,        b0[0], b0[1], b0[2], b0[3]);
            ldsm_x4(sb + boff0 + 8192 + so, b1r[0], b1r[1], b1r[2], b1r[3]);

            mma_f16(acc[0][0], a0[0], a0[1], a0[2], a0[3], b0[0],  b0[1]);
            mma_f16(acc[0][1], a0[0], a0[1], a0[2], a0[3], b0[2],  b0[3]);
            mma_f16(acc[0][2], a0[0], a0[1], a0[2], a0[3], b1r[0], b1r[1]);
            mma_f16(acc[0][3], a0[0], a0[1], a0[2], a0[3], b1r[2], b1r[3]);
            mma_f16(acc[1][0], a1[0], a1[1], a1[2], a1[3], b0[0],  b0[1]);
            mma_f16(acc[1][1], a1[0], a1[1], a1[2], a1[3], b0[2],  b0[3]);
            mma_f16(acc[1][2], a1[0], a1[1], a1[2], a1[3], b1r[0], b1r[1]);
            mma_f16(acc[1][3], a1[0], a1[1], a1[2], a1[3], b1r[2], b1r[3]);
        }

        // chunk epilogue: fold h -> relu(h + b1) . W2 into per-row partials
        int colb = ch * 64 + nw * 32 + 2 * t;
        #pragma unroll
        for (int nt = 0; nt < 4; nt++) {
            float bv0 = smB1[colb + nt * 8],     bv1 = smB1[colb + nt * 8 + 1];
            float wv0 = smW2[colb + nt * 8],     wv1 = smW2[colb + nt * 8 + 1];
            #pragma unroll
            for (int mt = 0; mt < 2; mt++) {
                part[mt * 2 + 0] += fmaxf(acc[mt][nt][0] + bv0, 0.f) * wv0
                                  + fmaxf(acc[mt][nt][1] + bv1, 0.f) * wv1;
                part[mt * 2 + 1] += fmaxf(acc[mt][nt][2] + bv0, 0.f) * wv0
                                  + fmaxf(acc[mt][nt][3] + bv1, 0.f) * wv1;
            }
        }
    }

    // reduce over the 4 lanes (t) that share each row
    #pragma unroll
    for (int p = 0; p < 4; p++) {
        part[p] += __shfl_xor_sync(0xffffffffu, part[p], 1);
        part[p] += __shfl_xor_sync(0xffffffffu, part[p], 2);
    }
    if (t == 0) {
        float* sc = (float*)(smem + SM_SC);
        atomicAdd(&sc[mw * 32 + g],      part[0]);
        atomicAdd(&sc[mw * 32 + 8 + g],  part[1]);
        atomicAdd(&sc[mw * 32 + 16 + g], part[2]);
        atomicAdd(&sc[mw * 32 + 24 + g], part[3]);
    }
    __syncthreads();
    if (tid < 128)
        g_scores[rowbase + tid] = ((float*)(smem + SM_SC))[tid] + __ldg(b2);
}

// ---------------- kernel 4: segment softmax + weighted pooling --------------
__global__ void __launch_bounds__(256)
k_pool(const float* __restrict__ x, float* __restrict__ out) {
    __shared__ float wbuf[1024];
    __shared__ float red[256];
    int g = blockIdx.x, t = threadIdx.x;
    int s0 = g_segstart[g], s1 = g_segstart[g + 1];

    // segment max, clamped at >= 0 (scatter-amax-into-zeros semantics)
    float m = 0.f;
    for (int i = s0 + t; i < s1; i += 256) m = fmaxf(m, g_scores[i]);
    red[t] = m; __syncthreads();
    #pragma unroll
    for (int st = 128; st > 0; st >>= 1) {
        if (t < st) red[t] = fmaxf(red[t], red[t + st]);
        __syncthreads();
    }
    m = red[0]; __syncthreads();

    float den = 0.f;
    float a0 = 0.f, a1 = 0.f, a2 = 0.f, a3 = 0.f;   // 4 independent chains
    for (int base = s0; base < s1; base += 1024) {
        int n = min(1024, s1 - base);
        for (int i = t; i < n; i += 256) {
            float e = __expf(g_scores[base + i] - m);
            wbuf[i] = e;
            den += e;
        }
        __syncthreads();
        const float* xb = x + (size_t)base * 256 + t;
        int i = 0;
        for (; i + 4 <= n; i += 4) {
            float v0 = __ldg(xb + (size_t)(i + 0) * 256);
            float v1 = __ldg(xb + (size_t)(i + 1) * 256);
            float v2 = __ldg(xb + (size_t)(i + 2) * 256);
            float v3 = __ldg(xb + (size_t)(i + 3) * 256);
            a0 = fmaf(v0, wbuf[i + 0], a0);
            a1 = fmaf(v1, wbuf[i + 1], a1);
            a2 = fmaf(v2, wbuf[i + 2], a2);
            a3 = fmaf(v3, wbuf[i + 3], a3);
        }
        for (; i < n; i++)
            a0 = fmaf(__ldg(xb + (size_t)i * 256), wbuf[i], a0);
        __syncthreads();
    }
    float acc = (a0 + a1) + (a2 + a3);

    red[t] = den; __syncthreads();
    #pragma unroll
    for (int st = 128; st > 0; st >>= 1) {
        if (t < st) red[t] += red[t + st];
        __syncthreads();
    }
    den = red[0];
    out[g * 256 + t] = acc / (den + 1e-9f);
}

// ---------------- launch ----------------------------------------------------
extern "C" void kernel_launch(void* const* d_in, const int* in_sizes, int n_in,
                              void* d_out, int out_size) {
    // Resolve inputs by element count (robust to ordering); b1 before W2.
    const float* x = 0; const float* W1 = 0; const float* b1 = 0;
    const float* W2 = 0; const float* b2 = 0; const void* batch = 0;
    for (int i = 0; i < n_in; i++) {
        switch (in_sizes[i]) {
            case 67108864: x = (const float*)d_in[i]; break;
            case 65536:    W1 = (const float*)d_in[i]; break;
            case 262144:   batch = d_in[i]; break;
            case 1:        b2 = (const float*)d_in[i]; break;
            case 256:
                if (!b1) b1 = (const float*)d_in[i];
                else     W2 = (const float*)d_in[i];
                break;
            default: break;
        }
    }
    if (!x)     x     = (const float*)d_in[0];
    if (!W1)    W1    = (const float*)d_in[1];
    if (!b1)    b1    = (const float*)d_in[2];
    if (!W2)    W2    = (const float*)d_in[3];
    if (!b2)    b2    = (const float*)d_in[4];
    if (!batch) batch = d_in[5];

    cudaFuncSetAttribute(k_scores, cudaFuncAttributeMaxDynamicSharedMemorySize,
                         SMEM_SCORES_TOTAL);

    k_w1t<<<KDIM, HID>>>(W1);
    k_bounds<<<5, 256>>>(batch);
    k_scores<<<NROWS / 128, 256, SMEM_SCORES_TOTAL>>>(x, b1, W2, b2);
    k_pool<<<NSEG, 256>>>(x, (float*)d_out);
}

// round 5
// speedup vs baseline: 1.6225x; 1.0303x over previous
#include <cuda_runtime.h>
#include <cuda_fp16.h>
#include <cstdint>

#define NROWS   262144
#define NSEG    1024
#define HID     256
#define KDIM    256

// ---------------- scratch (device globals: no allocations allowed) ----------
__device__ float  g_scores[NROWS];
__device__ __half g_w1t[HID * KDIM];          // W1^T as fp16, [n][k]
__device__ __half g_xh[(size_t)NROWS * KDIM]; // fp16 copy of x (written by k_scores)
__device__ int    g_segstart[NSEG + 1];

// ---------------- helpers ----------------------------------------------------
static __device__ __forceinline__ uint32_t smem_u32(const void* p) {
    uint32_t a;
    asm("{ .reg .u64 t; cvta.to.shared.u64 t, %1; cvt.u32.u64 %0, t; }"
        : "=r"(a) : "l"(p));
    return a;
}

static __device__ __forceinline__ void ldsm_x4(uint32_t a, uint32_t& r0, uint32_t& r1,
                                               uint32_t& r2, uint32_t& r3) {
    asm volatile("ldmatrix.sync.aligned.m8n8.x4.shared.b16 {%0,%1,%2,%3}, [%4];"
                 : "=r"(r0), "=r"(r1), "=r"(r2), "=r"(r3) : "r"(a));
}

static __device__ __forceinline__ void mma_f16(float* c,
                                               uint32_t a0, uint32_t a1, uint32_t a2, uint32_t a3,
                                               uint32_t b0, uint32_t b1) {
    asm volatile("mma.sync.aligned.m16n8k16.row.col.f32.f16.f16.f32 "
                 "{%0,%1,%2,%3}, {%4,%5,%6,%7}, {%8,%9}, {%0,%1,%2,%3};"
                 : "+f"(c[0]), "+f"(c[1]), "+f"(c[2]), "+f"(c[3])
                 : "r"(a0), "r"(a1), "r"(a2), "r"(a3), "r"(b0), "r"(b1));
}

static __device__ __forceinline__ uint32_t pack_h2(float a, float b) {
    __half2 h = __floats2half2_rn(a, b);
    return *(uint32_t*)&h;
}

// ---------------- kernel 1: W1^T -> fp16 [n][k] ------------------------------
__global__ void k_w1t(const float* __restrict__ W1) {
    int k = blockIdx.x, n = threadIdx.x;
    g_w1t[n * KDIM + k] = __float2half_rn(W1[k * HID + n]);
}

// ---------------- kernel 2: segment boundaries (batch sorted) ----------------
// batch may be int32 (JAX x64 disabled) or int64; detect on device.
__global__ void k_bounds(const void* __restrict__ batch_raw) {
    const int* b32 = (const int*)batch_raw;
    bool is64 = (b32[NROWS - 1] == 0) && (b32[NROWS - 3] == 0) &&
                (b32[NROWS - 5] == 0) && (b32[NROWS - 7] == 0);
    int g = blockIdx.x * blockDim.x + threadIdx.x;
    if (g > NSEG) return;
    int lo = 0, hi = NROWS;
    while (lo < hi) {
        int mid = (lo + hi) >> 1;
        long long v = is64 ? ((const long long*)batch_raw)[mid] : (long long)b32[mid];
        if (v < (long long)g) lo = mid + 1; else hi = mid;
    }
    g_segstart[g] = lo;
}

// ---------------- kernel 3: scores via mma.sync fp16 -------------------------
// Per CTA: M=128 rows, N=256 in 4 chunks of 64, K=256. 2 CTAs/SM.
// Also emits the fp16 copy of x for k_pool.
#define SM_A   0          // 128 x 256 fp16, swizzled           (65536)
#define SM_B   65536      // 64 x 256 fp16 chunk of W1^T        (32768)
#define SM_SC  98304      // 128 f32 partial scores             (512)
#define SM_B1  98816      // 256 f32                            (1024)
#define SM_W2  99840      // 256 f32                            (1024)
#define SMEM_SCORES_TOTAL 100864

__global__ void __launch_bounds__(256, 2)
k_scores(const float* __restrict__ x, const float* __restrict__ b1,
         const float* __restrict__ W2, const float* __restrict__ b2) {
    extern __shared__ char smem[];
    uint32_t sb = smem_u32(smem);
    int tid = threadIdx.x, wid = tid >> 5, lid = tid & 31;
    size_t rowbase = (size_t)blockIdx.x * 128;
    int mw = wid & 3, nw = wid >> 2;              // warp grid: 4 (M) x 2 (N)

    // preload B chunk 0 into registers (hides L2 latency behind A staging)
    const uint4* wp = (const uint4*)g_w1t;        // 2048 uint4 per 64-row chunk
    uint4 breg[8];
    #pragma unroll
    for (int i = 0; i < 8; i++) breg[i] = wp[tid + i * 256];

    // stage constants, zero score accumulator
    if (tid < 128) ((float*)(smem + SM_SC))[tid] = 0.f;
    ((float*)(smem + SM_B1))[tid] = b1[tid];
    ((float*)(smem + SM_W2))[tid] = W2[tid];

    // ---- stage A tile: 128x256 f32 -> fp16, swizzled; also write g_xh ----
    {
        const float4* xp = (const float4*)(x + rowbase * 256);
        uint4* xh_out = (uint4*)(g_xh + rowbase * 256);
        #pragma unroll
        for (int i = 0; i < 16; i++) {
            int cid = tid + i * 256;              // 0..4095 chunks of 8 elems
            int row = cid >> 5, c = cid & 31;
            float4 v0 = __ldg(&xp[row * 64 + c * 2]);
            float4 v1 = __ldg(&xp[row * 64 + c * 2 + 1]);
            uint4 hv;
            hv.x = pack_h2(v0.x, v0.y);
            hv.y = pack_h2(v0.z, v0.w);
            hv.z = pack_h2(v1.x, v1.y);
            hv.w = pack_h2(v1.z, v1.w);
            uint32_t off = row * 512 + ((c ^ (row & 7)) << 4);
            *(uint4*)(smem + SM_A + off) = hv;
            xh_out[row * 32 + c] = hv;            // coalesced fp16 copy of x
        }
    }

    // ---- per-lane fragment address invariants ----
    int g = lid >> 2, t = lid & 3, r8 = lid & 7, j = lid >> 3;
    int arow = mw * 32 + (j & 1) * 8 + r8;
    uint32_t aoff0 = SM_A + arow * 512;
    int arm = arow & 7, ac0 = j >> 1;
    int nloc = nw * 32 + (j >> 1) * 8 + r8;
    uint32_t boff0 = SM_B + nloc * 512;
    int bnm = nloc & 7, bc0 = j & 1;

    const float* smB1 = (const float*)(smem + SM_B1);
    const float* smW2 = (const float*)(smem + SM_W2);
    float part[4] = {0.f, 0.f, 0.f, 0.f};         // rows mw*32 + {g, g+8, 16+g, 24+g}

    for (int ch = 0; ch < 4; ch++) {
        __syncthreads();                          // prev B reads done / A staged
        // commit preloaded B chunk to smem (swizzled)
        #pragma unroll
        for (int i = 0; i < 8; i++) {
            int cid = tid + i * 256;              // == nl*32 + c
            int nl = cid >> 5, c = cid & 31;
            *(uint4*)(smem + SM_B + nl * 512 + ((c ^ (nl & 7)) << 4)) = breg[i];
        }
        // issue next chunk's loads now; latency hides under the MMA loop
        if (ch < 3) {
            #pragma unroll
            for (int i = 0; i < 8; i++)
                breg[i] = wp[(ch + 1) * 2048 + tid + i * 256];
        }
        __syncthreads();

        float acc[2][4][4];
        #pragma unroll
        for (int a = 0; a < 2; a++)
            #pragma unroll
            for (int b = 0; b < 4; b++)
                #pragma unroll
                for (int cc = 0; cc < 4; cc++) acc[a][b][cc] = 0.f;

        #pragma unroll 8
        for (int ks = 0; ks < 16; ks++) {
            uint32_t sa = (uint32_t)(((2 * ks + ac0) ^ arm) << 4);
            uint32_t so = (uint32_t)(((2 * ks + bc0) ^ bnm) << 4);
            uint32_t a0[4], a1[4], b0[4], b1r[4];
            ldsm_x4(sb + aoff0 + sa,        a0[0], a0[1], a0[2], a0[3]);
            ldsm_x4(sb + aoff0 + 8192 + sa, a1[0], a1[1], a1[2], a1[3]);
            ldsm_x4(sb + boff0 + so,        b0[0], b0[1], b0[2], b0[3]);
            ldsm_x4(sb + boff0 + 8192 + so, b1r[0], b1r[1], b1r[2], b1r[3]);

            mma_f16(acc[0][0], a0[0], a0[1], a0[2], a0[3], b0[0],  b0[1]);
            mma_f16(acc[0][1], a0[0], a0[1], a0[2], a0[3], b0[2],  b0[3]);
            mma_f16(acc[0][2], a0[0], a0[1], a0[2], a0[3], b1r[0], b1r[1]);
            mma_f16(acc[0][3], a0[0], a0[1], a0[2], a0[3], b1r[2], b1r[3]);
            mma_f16(acc[1][0], a1[0], a1[1], a1[2], a1[3], b0[0],  b0[1]);
            mma_f16(acc[1][1], a1[0], a1[1], a1[2], a1[3], b0[2],  b0[3]);
            mma_f16(acc[1][2], a1[0], a1[1], a1[2], a1[3], b1r[0], b1r[1]);
            mma_f16(acc[1][3], a1[0], a1[1], a1[2], a1[3], b1r[2], b1r[3]);
        }

        // chunk epilogue: fold h -> relu(h + b1) . W2 into per-row partials
        int colb = ch * 64 + nw * 32 + 2 * t;
        #pragma unroll
        for (int nt = 0; nt < 4; nt++) {
            float bv0 = smB1[colb + nt * 8],     bv1 = smB1[colb + nt * 8 + 1];
            float wv0 = smW2[colb + nt * 8],     wv1 = smW2[colb + nt * 8 + 1];
            #pragma unroll
            for (int mt = 0; mt < 2; mt++) {
                part[mt * 2 + 0] += fmaxf(acc[mt][nt][0] + bv0, 0.f) * wv0
                                  + fmaxf(acc[mt][nt][1] + bv1, 0.f) * wv1;
                part[mt * 2 + 1] += fmaxf(acc[mt][nt][2] + bv0, 0.f) * wv0
                                  + fmaxf(acc[mt][nt][3] + bv1, 0.f) * wv1;
            }
        }
    }

    // reduce over the 4 lanes (t) that share each row
    #pragma unroll
    for (int p = 0; p < 4; p++) {
        part[p] += __shfl_xor_sync(0xffffffffu, part[p], 1);
        part[p] += __shfl_xor_sync(0xffffffffu, part[p], 2);
    }
    if (t == 0) {
        float* sc = (float*)(smem + SM_SC);
        atomicAdd(&sc[mw * 32 + g],      part[0]);
        atomicAdd(&sc[mw * 32 + 8 + g],  part[1]);
        atomicAdd(&sc[mw * 32 + 16 + g], part[2]);
        atomicAdd(&sc[mw * 32 + 24 + g], part[3]);
    }
    __syncthreads();
    if (tid < 128)
        g_scores[rowbase + tid] = ((float*)(smem + SM_SC))[tid] + __ldg(b2);
}

// ---------------- kernel 4: segment softmax + weighted pooling (fp16 x) -----
// 256 threads = 2 row-groups x 128 half2 columns.
__global__ void __launch_bounds__(256)
k_pool(float* __restrict__ out) {
    __shared__ float wbuf[1024];
    __shared__ float red[256];
    __shared__ float red2x[128];
    __shared__ float red2y[128];
    int g = blockIdx.x, t = threadIdx.x;
    int rp = t >> 7, cp = t & 127;
    int s0 = g_segstart[g], s1 = g_segstart[g + 1];

    // segment max, clamped at >= 0 (scatter-amax-into-zeros semantics)
    float m = 0.f;
    for (int i = s0 + t; i < s1; i += 256) m = fmaxf(m, g_scores[i]);
    red[t] = m; __syncthreads();
    #pragma unroll
    for (int st = 128; st > 0; st >>= 1) {
        if (t < st) red[t] = fmaxf(red[t], red[t + st]);
        __syncthreads();
    }
    m = red[0]; __syncthreads();

    float den = 0.f;
    float ax0 = 0.f, ay0 = 0.f, ax1 = 0.f, ay1 = 0.f;   // 2 chains per component
    const __half2* xh2 = (const __half2*)g_xh;
    for (int base = s0; base < s1; base += 1024) {
        int n = min(1024, s1 - base);
        for (int i = t; i < n; i += 256) {
            float e = __expf(g_scores[base + i] - m);
            wbuf[i] = e;
            den += e;
        }
        __syncthreads();
        const __half2* xb = xh2 + (size_t)base * 128 + cp;
        int i = rp;
        for (; i + 2 < n; i += 4) {                     // rows i, i+2
            float2 v0 = __half22float2(xb[(size_t)i * 128]);
            float2 v1 = __half22float2(xb[(size_t)(i + 2) * 128]);
            float w0 = wbuf[i], w1 = wbuf[i + 2];
            ax0 = fmaf(v0.x, w0, ax0); ay0 = fmaf(v0.y, w0, ay0);
            ax1 = fmaf(v1.x, w1, ax1); ay1 = fmaf(v1.y, w1, ay1);
        }
        for (; i < n; i += 2) {
            float2 v = __half22float2(xb[(size_t)i * 128]);
            float w = wbuf[i];
            ax0 = fmaf(v.x, w, ax0); ay0 = fmaf(v.y, w, ay0);
        }
        __syncthreads();
    }
    float ax = ax0 + ax1, ay = ay0 + ay1;

    red[t] = den; __syncthreads();
    #pragma unroll
    for (int st = 128; st > 0; st >>= 1) {
        if (t < st) red[t] += red[t + st];
        __syncthreads();
    }
    den = red[0] + 1e-9f;
    __syncthreads();

    if (rp == 1) { red2x[cp] = ax; red2y[cp] = ay; }
    __syncthreads();
    if (rp == 0) {
        out[g * 256 + 2 * cp]     = (ax + red2x[cp]) / den;
        out[g * 256 + 2 * cp + 1] = (ay + red2y[cp]) / den;
    }
}

// ---------------- launch ----------------------------------------------------
extern "C" void kernel_launch(void* const* d_in, const int* in_sizes, int n_in,
                              void* d_out, int out_size) {
    // Resolve inputs by element count (robust to ordering); b1 before W2.
    const float* x = 0; const float* W1 = 0; const float* b1 = 0;
    const float* W2 = 0; const float* b2 = 0; const void* batch = 0;
    for (int i = 0; i < n_in; i++) {
        switch (in_sizes[i]) {
            case 67108864: x = (const float*)d_in[i]; break;
            case 65536:    W1 = (const float*)d_in[i]; break;
            case 262144:   batch = d_in[i]; break;
            case 1:        b2 = (const float*)d_in[i]; break;
            case 256:
                if (!b1) b1 = (const float*)d_in[i];
                else     W2 = (const float*)d_in[i];
                break;
            default: break;
        }
    }
    if (!x)     x     = (const float*)d_in[0];
    if (!W1)    W1    = (const float*)d_in[1];
    if (!b1)    b1    = (const float*)d_in[2];
    if (!W2)    W2    = (const float*)d_in[3];
    if (!b2)    b2    = (const float*)d_in[4];
    if (!batch) batch = d_in[5];

    cudaFuncSetAttribute(k_scores, cudaFuncAttributeMaxDynamicSharedMemorySize,
                         SMEM_SCORES_TOTAL);

    k_w1t<<<KDIM, HID>>>(W1);
    k_bounds<<<5, 256>>>(batch);
    k_scores<<<NROWS / 128, 256, SMEM_SCORES_TOTAL>>>(x, b1, W2, b2);
    k_pool<<<NSEG, 256>>>((float*)d_out);
}